// round 2
// baseline (speedup 1.0000x reference)
#include <cuda_runtime.h>
#include <math.h>

// ---------------------------------------------------------------------------
// Problem constants
// ---------------------------------------------------------------------------
namespace {
constexpr int B = 32, R = 29, S = 30, H = 768, NH = 12, DH = 64, FF = 3072;
constexpr int L = 12, D = 14, E = 15, RK = 8, H2 = 384;
constexpr int MROWS = B * S;          // 960
constexpr float SCALING = 2.0f;       // 16/8
}

// ---------------------------------------------------------------------------
// Global scratch (no allocations allowed)
// ---------------------------------------------------------------------------
__device__ float g_hs  [MROWS * H];
__device__ float g_xln [MROWS * H];
__device__ float g_qkv [MROWS * 3 * H];
__device__ float g_ctx [MROWS * H];
__device__ float g_attn[MROWS * H];
__device__ float g_res1[MROWS * H];
__device__ float g_y   [MROWS * H];
__device__ float g_bh  [MROWS * FF];
__device__ float g_bo  [MROWS * H];
__device__ float g_pooled[D * B * H];
__device__ float g_h1  [D * B * H2];
__device__ float g_act [B * D];
__device__ float g_cnt [D];
__device__ float g_aup [MROWS * E * RK];
__device__ float g_G   [MROWS * E * RK];
__device__ float g_adn [MROWS * E * RK];
__device__ float g_M   [E * RK * RK];
__device__ float g_w   [MROWS * E];

// ---------------------------------------------------------------------------
// Helpers
// ---------------------------------------------------------------------------
__device__ __forceinline__ float gelu_exact(float v) {
    return 0.5f * v * (1.0f + erff(v * 0.70710678118654752f));
}

// ---------------------------------------------------------------------------
// hs init: [cls ; region_features]
// ---------------------------------------------------------------------------
__global__ void init_hs_kernel(const float* __restrict__ region,
                               const float* __restrict__ cls) {
    int idx = blockIdx.x * blockDim.x + threadIdx.x;
    if (idx >= MROWS * H) return;
    int h = idx % H;
    int m = idx / H;
    int s = m % S;
    int b = m / S;
    g_hs[idx] = (s == 0) ? cls[h] : region[((long)b * R + (s - 1)) * H + h];
}

// ---------------------------------------------------------------------------
// LayerNorm (affine), one block per row
// ---------------------------------------------------------------------------
__global__ void ln_kernel(const float* __restrict__ x,
                          const float* __restrict__ w,
                          const float* __restrict__ b,
                          float* __restrict__ out,
                          int width, float eps) {
    int row = blockIdx.x;
    int t = threadIdx.x;
    const float* xr = x + (long)row * width;
    float* orow = out + (long)row * width;
    __shared__ float red[256];

    float s = 0.f;
    for (int i = t; i < width; i += 256) s += xr[i];
    red[t] = s; __syncthreads();
    for (int o = 128; o > 0; o >>= 1) { if (t < o) red[t] += red[t + o]; __syncthreads(); }
    float mu = red[0] / width;
    __syncthreads();

    float vs = 0.f;
    for (int i = t; i < width; i += 256) { float d = xr[i] - mu; vs += d * d; }
    red[t] = vs; __syncthreads();
    for (int o = 128; o > 0; o >>= 1) { if (t < o) red[t] += red[t + o]; __syncthreads(); }
    float var = red[0] / width;
    float rs = rsqrtf(var + eps);

    for (int i = t; i < width; i += 256)
        orow[i] = (xr[i] - mu) * rs * w[i] + b[i];
}

// ---------------------------------------------------------------------------
// Generic tiled SGEMM:  C[m,n] = epi( sum_k A[m,k] * W[n,k] + bias[n] ) (+res)
// A: (M,K) row-major, W: (N,K) row-major. Batched via blockIdx.z.
// ---------------------------------------------------------------------------
__global__ void gemm_kernel(const float* __restrict__ A,
                            const float* __restrict__ W,
                            const float* __restrict__ bias,
                            const float* __restrict__ res,
                            float* __restrict__ C,
                            int Mm, int Nn, int Kk,
                            long sA, long sW, long sB, long sC,
                            int do_gelu) {
    int z = blockIdx.z;
    A += (long)z * sA;
    W += (long)z * sW;
    C += (long)z * sC;
    if (bias) bias += (long)z * sB;
    if (res)  res  += (long)z * sC;

    __shared__ float As[16][65];
    __shared__ float Ws[16][65];

    int tx = threadIdx.x & 15;
    int ty = threadIdx.x >> 4;
    int m0 = blockIdx.y * 64;
    int n0 = blockIdx.x * 64;

    float acc[4][4];
#pragma unroll
    for (int i = 0; i < 4; i++)
#pragma unroll
        for (int j = 0; j < 4; j++) acc[i][j] = 0.f;

    for (int k0 = 0; k0 < Kk; k0 += 16) {
#pragma unroll
        for (int i = 0; i < 4; i++) {
            int idx = threadIdx.x + i * 256;
            int r = idx >> 4, c = idx & 15;
            int m = m0 + r;
            As[c][r] = (m < Mm) ? A[(long)m * Kk + k0 + c] : 0.f;
            int n = n0 + r;
            Ws[c][r] = (n < Nn) ? W[(long)n * Kk + k0 + c] : 0.f;
        }
        __syncthreads();
#pragma unroll
        for (int kk = 0; kk < 16; kk++) {
            float a[4], bb[4];
#pragma unroll
            for (int i = 0; i < 4; i++) a[i] = As[kk][ty * 4 + i];
#pragma unroll
            for (int j = 0; j < 4; j++) bb[j] = Ws[kk][tx * 4 + j];
#pragma unroll
            for (int i = 0; i < 4; i++)
#pragma unroll
                for (int j = 0; j < 4; j++)
                    acc[i][j] += a[i] * bb[j];
        }
        __syncthreads();
    }

#pragma unroll
    for (int i = 0; i < 4; i++) {
        int m = m0 + ty * 4 + i;
        if (m >= Mm) continue;
#pragma unroll
        for (int j = 0; j < 4; j++) {
            int n = n0 + tx * 4 + j;
            if (n >= Nn) continue;
            float v = acc[i][j];
            if (bias) v += bias[n];
            if (do_gelu) v = gelu_exact(v);
            if (res) v += res[(long)m * Nn + n];
            C[(long)m * Nn + n] = v;
        }
    }
}

// ---------------------------------------------------------------------------
// Attention: one block per (batch, head). S=30, DH=64.
// ---------------------------------------------------------------------------
__global__ void attn_kernel() {
    int b = blockIdx.x;
    int n = blockIdx.y;
    __shared__ float q[S][DH], k[S][DH], v[S][DH];
    __shared__ float sc[S][S + 2];
    int t = threadIdx.x;   // 256

    for (int i = t; i < S * DH; i += 256) {
        int s = i / DH, d = i % DH;
        long base = ((long)(b * S + s)) * (3 * H) + n * DH + d;
        q[s][d] = g_qkv[base];
        k[s][d] = g_qkv[base + H];
        v[s][d] = g_qkv[base + 2 * H];
    }
    __syncthreads();

    for (int p = t; p < S * S; p += 256) {
        int qi = p / S, ki = p % S;
        float s = 0.f;
#pragma unroll
        for (int d = 0; d < DH; d++) s += q[qi][d] * k[ki][d];
        sc[qi][ki] = s * 0.125f;   // 1/sqrt(64)
    }
    __syncthreads();

    if (t < S) {
        float mx = -1e30f;
        for (int ki = 0; ki < S; ki++) mx = fmaxf(mx, sc[t][ki]);
        float sum = 0.f;
        for (int ki = 0; ki < S; ki++) { float e = __expf(sc[t][ki] - mx); sc[t][ki] = e; sum += e; }
        float inv = 1.f / sum;
        for (int ki = 0; ki < S; ki++) sc[t][ki] *= inv;
    }
    __syncthreads();

    for (int p = t; p < S * DH; p += 256) {
        int qi = p / DH, d = p % DH;
        float s = 0.f;
#pragma unroll
        for (int ki = 0; ki < S; ki++) s += sc[qi][ki] * v[ki][d];
        g_ctx[((long)(b * S + qi)) * H + n * DH + d] = s;
    }
}

// ---------------------------------------------------------------------------
// res1 = attn_out + hs
// ---------------------------------------------------------------------------
__global__ void add_kernel(const float* __restrict__ a,
                           const float* __restrict__ b,
                           float* __restrict__ o, int nelem) {
    int idx = blockIdx.x * blockDim.x + threadIdx.x;
    if (idx < nelem) o[idx] = a[idx] + b[idx];
}

// ---------------------------------------------------------------------------
// pooled_t[d][b][h] = sum_r attn[b,1+r,h]*mask[r,d] / max(cnt_d,1); also g_cnt
// ---------------------------------------------------------------------------
__global__ void pool_kernel(const float* __restrict__ mask) {
    int d = blockIdx.x;
    int b = blockIdx.y;
    int t = threadIdx.x;   // 256
    __shared__ float mk[R];
    __shared__ float inv;
    if (t < R) mk[t] = mask[t * D + d];
    __syncthreads();
    if (t == 0) {
        float c = 0.f;
        for (int r = 0; r < R; r++) c += mk[r];
        if (b == 0) g_cnt[d] = c;
        inv = 1.f / fmaxf(c, 1.f);
    }
    __syncthreads();
    for (int h = t; h < H; h += 256) {
        float s = 0.f;
#pragma unroll 1
        for (int r = 0; r < R; r++)
            s += g_attn[((long)(b * S + 1 + r)) * H + h] * mk[r];
        g_pooled[((long)(d * B + b)) * H + h] = s * inv;
    }
}

// ---------------------------------------------------------------------------
// classifier head: LN(eps1e-5) + gelu + dot(w2) + b2 -> active bit
// one block per (d, b), 128 threads
// ---------------------------------------------------------------------------
__global__ void cls_head_kernel(const float* __restrict__ lnw,
                                const float* __restrict__ lnb,
                                const float* __restrict__ w2,
                                const float* __restrict__ b2) {
    int d = blockIdx.x;
    int b = blockIdx.y;
    int t = threadIdx.x;   // 128
    __shared__ float red[128];
    const float* row = g_h1 + ((long)(d * B + b)) * H2;

    float s = 0.f;
    for (int i = t; i < H2; i += 128) s += row[i];
    red[t] = s; __syncthreads();
    for (int o = 64; o > 0; o >>= 1) { if (t < o) red[t] += red[t + o]; __syncthreads(); }
    float mu = red[0] / H2;
    __syncthreads();

    float vs = 0.f;
    for (int i = t; i < H2; i += 128) { float dd = row[i] - mu; vs += dd * dd; }
    red[t] = vs; __syncthreads();
    for (int o = 64; o > 0; o >>= 1) { if (t < o) red[t] += red[t + o]; __syncthreads(); }
    float var = red[0] / H2;
    float rs = rsqrtf(var + 1e-5f);
    __syncthreads();

    float dot = 0.f;
    for (int i = t; i < H2; i += 128) {
        float v = (row[i] - mu) * rs * lnw[d * H2 + i] + lnb[d * H2 + i];
        v = gelu_exact(v);
        dot += v * w2[d * H2 + i];
    }
    red[t] = dot; __syncthreads();
    for (int o = 64; o > 0; o >>= 1) { if (t < o) red[t] += red[t + o]; __syncthreads(); }
    if (t == 0) {
        float pred = red[0] + b2[d];
        g_act[b * D + d] = (g_cnt[d] > 0.f && pred > 0.f) ? 1.f : 0.f;
    }
}

// ---------------------------------------------------------------------------
// expert weights w[b,s,e]
// ---------------------------------------------------------------------------
__global__ void w_kernel(const float* __restrict__ mask) {
    int idx = blockIdx.x * blockDim.x + threadIdx.x;
    if (idx >= MROWS) return;
    int s = idx % S;
    int b = idx / S;
    float a[E];
    float sum = 1.f;
    for (int d = 0; d < D; d++) {
        float v = 0.f;
        if (s > 0 && mask[(s - 1) * D + d] > 0.f) v = g_act[b * D + d];
        a[d] = v;
        sum += v;
    }
    a[D] = 1.f;
    float inv = 1.f / sum;     // sum >= 1, so clip(sum,1)=sum
    for (int e = 0; e < E; e++) g_w[idx * E + e] = a[e] * inv;
}

// ---------------------------------------------------------------------------
// M[e,r,r'] = sum_f A_down[e,r,f] * B_up[e,f,r']
// ---------------------------------------------------------------------------
__global__ void mmat_kernel(const float* __restrict__ Adown,
                            const float* __restrict__ Bup) {
    int e  = blockIdx.x >> 6;
    int p  = blockIdx.x & 63;
    int r  = p >> 3;
    int rp = p & 7;
    int t = threadIdx.x;   // 128
    __shared__ float red[128];
    const float* ad = Adown + ((long)e * RK + r) * FF;
    const float* bu = Bup + (long)e * FF * RK + rp;
    float s = 0.f;
    for (int f = t; f < FF; f += 128) s += ad[f] * bu[(long)f * RK];
    red[t] = s; __syncthreads();
    for (int o = 64; o > 0; o >>= 1) { if (t < o) red[t] += red[t + o]; __syncthreads(); }
    if (t == 0) g_M[e * 64 + p] = red[0];
}

// ---------------------------------------------------------------------------
// a_dn = G + SCALING * M @ a_up   (per b,s,e : 8x8 matvec)
// ---------------------------------------------------------------------------
__global__ void adn_kernel() {
    int idx = blockIdx.x * 256 + threadIdx.x;
    if (idx >= MROWS * E * RK) return;
    int c = idx % (E * RK);
    int m = idx / (E * RK);
    int e = c / RK, r = c % RK;
    float s = g_G[idx];
    const float* mrow = g_M + e * 64 + r * 8;
    const float* au = g_aup + (long)m * (E * RK) + e * RK;
#pragma unroll
    for (int rp = 0; rp < 8; rp++) s += SCALING * mrow[rp] * au[rp];
    g_adn[idx] = s;
}

// ---------------------------------------------------------------------------
// Mixture epilogue: per token-row, for each active expert compute
// v = base_out + SCALING * B_down @ a_dn, LN_noaffine(eps 1e-5), weighted sum,
// then hs = final + res1.
// ---------------------------------------------------------------------------
__global__ void mix_kernel(const float* __restrict__ Bdown) {
    int m = blockIdx.x;
    int t = threadIdx.x;   // 256
    __shared__ float wsh[E];
    __shared__ float adn[E * RK];
    __shared__ float bos[H];
    __shared__ float red[256];

    if (t < E) wsh[t] = g_w[m * E + t];
    if (t < E * RK) adn[t] = g_adn[(long)m * (E * RK) + t];
    for (int i = t; i < H; i += 256) bos[i] = g_bo[(long)m * H + i];
    __syncthreads();

    float acc[3] = {0.f, 0.f, 0.f};

    for (int e = 0; e < E; e++) {
        float we = wsh[e];
        if (we == 0.f) continue;    // uniform branch (wsh in smem)
        float v[3];
        float ssum = 0.f;
#pragma unroll
        for (int i = 0; i < 3; i++) {
            int h = t + i * 256;
            const float* bd = Bdown + ((long)e * H + h) * RK;
            float l = 0.f;
#pragma unroll
            for (int r2 = 0; r2 < 8; r2++) l += bd[r2] * adn[e * RK + r2];
            v[i] = bos[h] + SCALING * l;
            ssum += v[i];
        }
        red[t] = ssum; __syncthreads();
        for (int o = 128; o > 0; o >>= 1) { if (t < o) red[t] += red[t + o]; __syncthreads(); }
        float mu = red[0] * (1.0f / H);
        __syncthreads();

        float vsum = 0.f;
#pragma unroll
        for (int i = 0; i < 3; i++) { float dd = v[i] - mu; vsum += dd * dd; }
        red[t] = vsum; __syncthreads();
        for (int o = 128; o > 0; o >>= 1) { if (t < o) red[t] += red[t + o]; __syncthreads(); }
        float var = red[0] * (1.0f / H);
        __syncthreads();
        float rs = rsqrtf(var + 1e-5f);
#pragma unroll
        for (int i = 0; i < 3; i++) acc[i] += we * (v[i] - mu) * rs;
    }

#pragma unroll
    for (int i = 0; i < 3; i++) {
        int h = t + i * 256;
        g_hs[(long)m * H + h] = acc[i] + g_res1[(long)m * H + h];
    }
}

// ---------------------------------------------------------------------------
// Host side
// ---------------------------------------------------------------------------
static void launch_gemm(const float* A, const float* W, const float* bias,
                        const float* res, float* C, int M, int N, int K,
                        int do_gelu, int batch = 1,
                        long sA = 0, long sW = 0, long sB = 0, long sC = 0) {
    dim3 grid((N + 63) / 64, (M + 63) / 64, batch);
    gemm_kernel<<<grid, 256>>>(A, W, bias, res, C, M, N, K, sA, sW, sB, sC, do_gelu);
}

extern "C" void kernel_launch(void* const* d_in, const int* in_sizes, int n_in,
                              void* d_out, int out_size) {
    const float* region = (const float*)d_in[0];
    const float* mask   = (const float*)d_in[1];
    const float* cls    = (const float*)d_in[2];
    const float* ln1w   = (const float*)d_in[3];
    const float* ln1b   = (const float*)d_in[4];
    const float* qkvw   = (const float*)d_in[5];
    const float* qkvb   = (const float*)d_in[6];
    const float* aow    = (const float*)d_in[7];
    const float* aob    = (const float*)d_in[8];
    const float* ln2w   = (const float*)d_in[9];
    const float* ln2b   = (const float*)d_in[10];
    const float* fw1    = (const float*)d_in[11];
    const float* fb1    = (const float*)d_in[12];
    const float* fw2    = (const float*)d_in[13];
    const float* fb2    = (const float*)d_in[14];
    const float* cw1    = (const float*)d_in[15];
    const float* cb1    = (const float*)d_in[16];
    const float* clnw   = (const float*)d_in[17];
    const float* clnb   = (const float*)d_in[18];
    const float* cw2    = (const float*)d_in[19];
    const float* cb2    = (const float*)d_in[20];
    const float* lAu    = (const float*)d_in[21];
    const float* lBu    = (const float*)d_in[22];
    const float* lAd    = (const float*)d_in[23];
    const float* lBd    = (const float*)d_in[24];
    const float* flw    = (const float*)d_in[25];
    const float* flb    = (const float*)d_in[26];
    float* out = (float*)d_out;

    float *hs, *xln, *qkv, *ctx, *attn, *res1, *y, *bh, *bo, *pooled, *h1, *aup, *G;
    cudaGetSymbolAddress((void**)&hs,   g_hs);
    cudaGetSymbolAddress((void**)&xln,  g_xln);
    cudaGetSymbolAddress((void**)&qkv,  g_qkv);
    cudaGetSymbolAddress((void**)&ctx,  g_ctx);
    cudaGetSymbolAddress((void**)&attn, g_attn);
    cudaGetSymbolAddress((void**)&res1, g_res1);
    cudaGetSymbolAddress((void**)&y,    g_y);
    cudaGetSymbolAddress((void**)&bh,   g_bh);
    cudaGetSymbolAddress((void**)&bo,   g_bo);
    cudaGetSymbolAddress((void**)&pooled, g_pooled);
    cudaGetSymbolAddress((void**)&h1,   g_h1);
    cudaGetSymbolAddress((void**)&aup,  g_aup);
    cudaGetSymbolAddress((void**)&G,    g_G);

    const int NE = MROWS * H;   // 737280

    init_hs_kernel<<<(NE + 255) / 256, 256>>>(region, cls);

    for (int i = 0; i < L; i++) {
        const int j = i / 2;

        // x_ln = LN(hs, ln1)
        ln_kernel<<<MROWS, 256>>>(hs, ln1w + (long)i * H, ln1b + (long)i * H, xln, H, 1e-12f);

        // qkv = x_ln @ qkv_w[i]^T + qkv_b[i]
        launch_gemm(xln, qkvw + (long)i * 3 * H * H, qkvb + (long)i * 3 * H,
                    nullptr, qkv, MROWS, 3 * H, H, 0);

        // attention -> ctx
        attn_kernel<<<dim3(B, NH), 256>>>();

        // attn_out = ctx @ ow^T + ob
        launch_gemm(ctx, aow + (long)i * H * H, aob + (long)i * H,
                    nullptr, attn, MROWS, H, H, 0);

        // res1 = attn_out + hs
        add_kernel<<<(NE + 255) / 256, 256>>>(attn, hs, res1, NE);

        // y = LN(res1, ln2)
        ln_kernel<<<MROWS, 256>>>(res1, ln2w + (long)i * H, ln2b + (long)i * H, y, H, 1e-12f);

        // base_hidden = gelu(y @ w1^T + b1)
        launch_gemm(y, fw1 + (long)i * FF * H, fb1 + (long)i * FF,
                    nullptr, bh, MROWS, FF, H, 1);

        if (i % 2 == 1) {
            // hs = base_hidden @ w2^T + b2 + res1
            launch_gemm(bh, fw2 + (long)i * H * FF, fb2 + (long)i * H,
                        res1, hs, MROWS, H, FF, 0);
        } else {
            // base_out (no residual)
            launch_gemm(bh, fw2 + (long)i * H * FF, fb2 + (long)i * H,
                        nullptr, bo, MROWS, H, FF, 0);

            // ---- classifier ----
            pool_kernel<<<dim3(D, B), 256>>>(mask);
            launch_gemm(pooled, cw1 + (long)j * D * H2 * H, cb1 + (long)j * D * H2,
                        nullptr, h1, B, H2, H, 0,
                        D, (long)B * H, (long)H2 * H, (long)H2, (long)B * H2);
            cls_head_kernel<<<dim3(D, B), 128>>>(clnw + (long)j * D * H2,
                                                 clnb + (long)j * D * H2,
                                                 cw2 + (long)j * D * H2,
                                                 cb2 + (long)j * D);
            w_kernel<<<(MROWS + 127) / 128, 128>>>(mask);

            // ---- LoRA (factored, no (b,s,e,FF) tensor) ----
            launch_gemm(y, lAu + (long)j * E * RK * H, nullptr,
                        nullptr, aup, MROWS, E * RK, H, 0);
            launch_gemm(bh, lAd + (long)j * E * RK * FF, nullptr,
                        nullptr, G, MROWS, E * RK, FF, 0);
            mmat_kernel<<<E * 64, 128>>>(lAd + (long)j * E * RK * FF,
                                         lBu + (long)j * E * FF * RK);
            adn_kernel<<<(MROWS * E * RK + 255) / 256, 256>>>();
            mix_kernel<<<MROWS, 256>>>(lBd + (long)j * E * H * RK);
        }
    }

    // final layernorm -> output
    ln_kernel<<<MROWS, 256>>>(hs, flw, flb, out, H, 1e-12f);
}

// round 3
// speedup vs baseline: 2.4061x; 2.4061x over previous
#include <cuda_runtime.h>
#include <cuda_bf16.h>
#include <math.h>
#include <stdint.h>

// ---------------------------------------------------------------------------
// Problem constants
// ---------------------------------------------------------------------------
namespace {
constexpr int B = 32, R = 29, S = 30, H = 768, NH = 12, DH = 64, FF = 3072;
constexpr int L = 12, D = 14, E = 15, RK = 8, H2 = 384;
constexpr int MROWS = B * S;          // 960
constexpr float SCALING = 2.0f;       // 16/8
}

// ---------------------------------------------------------------------------
// Global scratch (no allocations allowed)
// ---------------------------------------------------------------------------
__device__ float g_hs  [MROWS * H];
__device__ float g_xln [MROWS * H];
__device__ float g_qkv [MROWS * 3 * H];
__device__ float g_ctx [MROWS * H];
__device__ float g_res1[MROWS * H];
__device__ float g_y   [MROWS * H];
__device__ float g_bh  [MROWS * FF];
__device__ float g_bo  [MROWS * H];
__device__ float g_pooled[D * B * H];
__device__ float g_h1  [D * B * H2];
__device__ float g_act [B * D];
__device__ float g_cnt [D];
__device__ float g_aup [MROWS * E * RK];
__device__ float g_G   [MROWS * E * RK];
__device__ float g_adn [MROWS * E * RK];
__device__ float g_M   [E * RK * RK];
__device__ float g_w   [MROWS * E];

// ---------------------------------------------------------------------------
// Helpers
// ---------------------------------------------------------------------------
__device__ __forceinline__ float gelu_exact(float v) {
    return 0.5f * v * (1.0f + erff(v * 0.70710678118654752f));
}

__device__ __forceinline__ void mma16816(float c[4], const uint32_t a[4],
                                         uint32_t b0, uint32_t b1) {
    asm volatile(
        "mma.sync.aligned.m16n8k16.row.col.f32.bf16.bf16.f32 "
        "{%0,%1,%2,%3}, {%4,%5,%6,%7}, {%8,%9}, {%0,%1,%2,%3};\n"
        : "+f"(c[0]), "+f"(c[1]), "+f"(c[2]), "+f"(c[3])
        : "r"(a[0]), "r"(a[1]), "r"(a[2]), "r"(a[3]), "r"(b0), "r"(b1));
}

__device__ __forceinline__ uint32_t lds32(const __nv_bfloat16* p) {
    return *reinterpret_cast<const uint32_t*>(p);
}

// ---------------------------------------------------------------------------
// hs init: [cls ; region_features]
// ---------------------------------------------------------------------------
__global__ void init_hs_kernel(const float* __restrict__ region,
                               const float* __restrict__ cls) {
    int idx = blockIdx.x * blockDim.x + threadIdx.x;
    if (idx >= MROWS * H) return;
    int h = idx % H;
    int m = idx / H;
    int s = m % S;
    int b = m / S;
    g_hs[idx] = (s == 0) ? cls[h] : region[((long)b * R + (s - 1)) * H + h];
}

// ---------------------------------------------------------------------------
// LayerNorm (affine), one block per row
// ---------------------------------------------------------------------------
__global__ void ln_kernel(const float* __restrict__ x,
                          const float* __restrict__ w,
                          const float* __restrict__ b,
                          float* __restrict__ out,
                          int width, float eps) {
    int row = blockIdx.x;
    int t = threadIdx.x;
    const float* xr = x + (long)row * width;
    float* orow = out + (long)row * width;
    __shared__ float red[256];

    float s = 0.f;
    for (int i = t; i < width; i += 256) s += xr[i];
    red[t] = s; __syncthreads();
    for (int o = 128; o > 0; o >>= 1) { if (t < o) red[t] += red[t + o]; __syncthreads(); }
    float mu = red[0] / width;
    __syncthreads();

    float vs = 0.f;
    for (int i = t; i < width; i += 256) { float d = xr[i] - mu; vs += d * d; }
    red[t] = vs; __syncthreads();
    for (int o = 128; o > 0; o >>= 1) { if (t < o) red[t] += red[t + o]; __syncthreads(); }
    float var = red[0] / width;
    float rs = rsqrtf(var + eps);

    for (int i = t; i < width; i += 256)
        orow[i] = (xr[i] - mu) * rs * w[i] + b[i];
}

// ---------------------------------------------------------------------------
// Tensor-core GEMM via mma.sync bf16 with hi/lo error split (~fp32 accurate).
// C[m,n] = epi( sum_k A[m,k]*W[n,k] + bias[n] ) (+res).  A:(M,K) W:(N,K) rm.
// Block tile 64 x BN x 32, 4 warps (128 threads). Requires K % 32 == 0.
// ---------------------------------------------------------------------------
template<int BN>
__global__ __launch_bounds__(128)
void mma_gemm_kernel(const float* __restrict__ A,
                     const float* __restrict__ W,
                     const float* __restrict__ bias,
                     const float* __restrict__ res,
                     float* __restrict__ C,
                     int Mm, int Nn, int Kk,
                     long sA, long sW, long sB, long sC,
                     int do_gelu) {
    constexpr int LDS = 40;                 // 32 + 8 pad (bank-conflict free)
    constexpr int NT = BN / 16;             // n-tiles (8 wide) per warp
    constexpr int AITER = 4;                // 64 rows * 8 f4 / 128 thr
    constexpr int BITER = BN * 8 / 128;

    int z = blockIdx.z;
    A += (long)z * sA;
    W += (long)z * sW;
    C += (long)z * sC;
    if (bias) bias += (long)z * sB;
    if (res)  res  += (long)z * sC;

    __shared__ __nv_bfloat16 sAhi[64 * LDS], sAlo[64 * LDS];
    __shared__ __nv_bfloat16 sBhi[BN * LDS], sBlo[BN * LDS];

    const int t = threadIdx.x;
    const int w = t >> 5;
    const int lane = t & 31;
    const int wm = (w & 1) * 32;
    const int wn = (w >> 1) * (BN / 2);
    const int grp = lane >> 2;
    const int tid4 = lane & 3;
    const int m0 = blockIdx.y * 64;
    const int n0 = blockIdx.x * BN;

    float acc[2][NT][4];
#pragma unroll
    for (int i = 0; i < 2; i++)
#pragma unroll
        for (int j = 0; j < NT; j++)
#pragma unroll
            for (int q = 0; q < 4; q++) acc[i][j][q] = 0.f;

    float4 aReg[AITER], bReg[BITER];

    // prologue loads (k0 = 0)
#pragma unroll
    for (int i = 0; i < AITER; i++) {
        int idx = t + 128 * i;
        int row = idx >> 3, c4 = (idx & 7) * 4;
        int gm = m0 + row;
        aReg[i] = (gm < Mm) ? *reinterpret_cast<const float4*>(A + (long)gm * Kk + c4)
                            : make_float4(0.f, 0.f, 0.f, 0.f);
    }
#pragma unroll
    for (int i = 0; i < BITER; i++) {
        int idx = t + 128 * i;
        int row = idx >> 3, c4 = (idx & 7) * 4;
        int gn = n0 + row;
        bReg[i] = (gn < Nn) ? *reinterpret_cast<const float4*>(W + (long)gn * Kk + c4)
                            : make_float4(0.f, 0.f, 0.f, 0.f);
    }

    for (int k0 = 0; k0 < Kk; k0 += 32) {
        // convert + store staged regs to smem
#pragma unroll
        for (int i = 0; i < AITER; i++) {
            int idx = t + 128 * i;
            int row = idx >> 3, c4 = (idx & 7) * 4;
            const float* v = reinterpret_cast<const float*>(&aReg[i]);
#pragma unroll
            for (int q = 0; q < 4; q++) {
                __nv_bfloat16 hi = __float2bfloat16(v[q]);
                sAhi[row * LDS + c4 + q] = hi;
                sAlo[row * LDS + c4 + q] = __float2bfloat16(v[q] - __bfloat162float(hi));
            }
        }
#pragma unroll
        for (int i = 0; i < BITER; i++) {
            int idx = t + 128 * i;
            int row = idx >> 3, c4 = (idx & 7) * 4;
            const float* v = reinterpret_cast<const float*>(&bReg[i]);
#pragma unroll
            for (int q = 0; q < 4; q++) {
                __nv_bfloat16 hi = __float2bfloat16(v[q]);
                sBhi[row * LDS + c4 + q] = hi;
                sBlo[row * LDS + c4 + q] = __float2bfloat16(v[q] - __bfloat162float(hi));
            }
        }
        __syncthreads();

        // prefetch next tile
        if (k0 + 32 < Kk) {
            int kn = k0 + 32;
#pragma unroll
            for (int i = 0; i < AITER; i++) {
                int idx = t + 128 * i;
                int row = idx >> 3, c4 = (idx & 7) * 4;
                int gm = m0 + row;
                aReg[i] = (gm < Mm) ? *reinterpret_cast<const float4*>(A + (long)gm * Kk + kn + c4)
                                    : make_float4(0.f, 0.f, 0.f, 0.f);
            }
#pragma unroll
            for (int i = 0; i < BITER; i++) {
                int idx = t + 128 * i;
                int row = idx >> 3, c4 = (idx & 7) * 4;
                int gn = n0 + row;
                bReg[i] = (gn < Nn) ? *reinterpret_cast<const float4*>(W + (long)gn * Kk + kn + c4)
                                    : make_float4(0.f, 0.f, 0.f, 0.f);
            }
        }

        // compute: two k16 steps
#pragma unroll
        for (int kk = 0; kk < 32; kk += 16) {
            uint32_t ah[2][4], al[2][4];
#pragma unroll
            for (int mt = 0; mt < 2; mt++) {
                int r0 = wm + mt * 16 + grp;
                int kp = kk + tid4 * 2;
                ah[mt][0] = lds32(sAhi + r0 * LDS + kp);
                ah[mt][1] = lds32(sAhi + (r0 + 8) * LDS + kp);
                ah[mt][2] = lds32(sAhi + r0 * LDS + kp + 8);
                ah[mt][3] = lds32(sAhi + (r0 + 8) * LDS + kp + 8);
                al[mt][0] = lds32(sAlo + r0 * LDS + kp);
                al[mt][1] = lds32(sAlo + (r0 + 8) * LDS + kp);
                al[mt][2] = lds32(sAlo + r0 * LDS + kp + 8);
                al[mt][3] = lds32(sAlo + (r0 + 8) * LDS + kp + 8);
            }
#pragma unroll
            for (int nt = 0; nt < NT; nt++) {
                int c0 = wn + nt * 8 + grp;
                int kp = kk + tid4 * 2;
                uint32_t bh0 = lds32(sBhi + c0 * LDS + kp);
                uint32_t bh1 = lds32(sBhi + c0 * LDS + kp + 8);
                uint32_t bl0 = lds32(sBlo + c0 * LDS + kp);
                uint32_t bl1 = lds32(sBlo + c0 * LDS + kp + 8);
#pragma unroll
                for (int mt = 0; mt < 2; mt++) {
                    mma16816(acc[mt][nt], ah[mt], bh0, bh1);
                    mma16816(acc[mt][nt], ah[mt], bl0, bl1);
                    mma16816(acc[mt][nt], al[mt], bh0, bh1);
                }
            }
        }
        __syncthreads();
    }

    // epilogue
#pragma unroll
    for (int mt = 0; mt < 2; mt++) {
#pragma unroll
        for (int nt = 0; nt < NT; nt++) {
            int row0 = m0 + wm + mt * 16 + grp;
            int col = n0 + wn + nt * 8 + tid4 * 2;
#pragma unroll
            for (int half = 0; half < 2; half++) {
                int row = row0 + half * 8;
                if (row >= Mm) continue;
#pragma unroll
                for (int q = 0; q < 2; q++) {
                    int c = col + q;
                    if (c >= Nn) continue;
                    float v = acc[mt][nt][half * 2 + q];
                    if (bias) v += bias[c];
                    if (do_gelu) v = gelu_exact(v);
                    if (res) v += res[(long)row * Nn + c];
                    C[(long)row * Nn + c] = v;
                }
            }
        }
    }
}

// ---------------------------------------------------------------------------
// Attention: one block per (batch, head). S=30, DH=64.
// ---------------------------------------------------------------------------
__global__ void attn_kernel() {
    int b = blockIdx.x;
    int n = blockIdx.y;
    __shared__ float q[S][DH], k[S][DH], v[S][DH];
    __shared__ float sc[S][S + 2];
    int t = threadIdx.x;   // 256

    for (int i = t; i < S * DH; i += 256) {
        int s = i / DH, d = i % DH;
        long base = ((long)(b * S + s)) * (3 * H) + n * DH + d;
        q[s][d] = g_qkv[base];
        k[s][d] = g_qkv[base + H];
        v[s][d] = g_qkv[base + 2 * H];
    }
    __syncthreads();

    for (int p = t; p < S * S; p += 256) {
        int qi = p / S, ki = p % S;
        float s = 0.f;
#pragma unroll
        for (int d = 0; d < DH; d++) s += q[qi][d] * k[ki][d];
        sc[qi][ki] = s * 0.125f;   // 1/sqrt(64)
    }
    __syncthreads();

    if (t < S) {
        float mx = -1e30f;
        for (int ki = 0; ki < S; ki++) mx = fmaxf(mx, sc[t][ki]);
        float sum = 0.f;
        for (int ki = 0; ki < S; ki++) { float e = __expf(sc[t][ki] - mx); sc[t][ki] = e; sum += e; }
        float inv = 1.f / sum;
        for (int ki = 0; ki < S; ki++) sc[t][ki] *= inv;
    }
    __syncthreads();

    for (int p = t; p < S * DH; p += 256) {
        int qi = p / DH, d = p % DH;
        float s = 0.f;
#pragma unroll
        for (int ki = 0; ki < S; ki++) s += sc[qi][ki] * v[ki][d];
        g_ctx[((long)(b * S + qi)) * H + n * DH + d] = s;
    }
}

// ---------------------------------------------------------------------------
// pooled_t[d][b][h] = sum_r res_path... uses attn_out == res1 - hs? No:
// pooled uses attn_out[:,1:,:]. attn_out = res1 - hs_prev; we keep attn in
// res1 before residual? Simpler: recompute from res1 and hs is gone. So we
// pool from (res1 - hs_old)?  We fused res1 = attn + hs, so store attn_out
// implicitly: pool reads res1 - hs. hs still holds pre-layer value at pool
// time (hs only rewritten at layer end). 
// ---------------------------------------------------------------------------
__global__ void pool_kernel(const float* __restrict__ mask) {
    int d = blockIdx.x;
    int b = blockIdx.y;
    int t = threadIdx.x;   // 256
    __shared__ float mk[R];
    __shared__ float inv;
    if (t < R) mk[t] = mask[t * D + d];
    __syncthreads();
    if (t == 0) {
        float c = 0.f;
        for (int r = 0; r < R; r++) c += mk[r];
        if (b == 0) g_cnt[d] = c;
        inv = 1.f / fmaxf(c, 1.f);
    }
    __syncthreads();
    for (int h = t; h < H; h += 256) {
        float s = 0.f;
#pragma unroll 1
        for (int r = 0; r < R; r++) {
            long idx = ((long)(b * S + 1 + r)) * H + h;
            s += (g_res1[idx] - g_hs[idx]) * mk[r];
        }
        g_pooled[((long)(d * B + b)) * H + h] = s * inv;
    }
}

// ---------------------------------------------------------------------------
// classifier head: LN(eps1e-5) + gelu + dot(w2) + b2 -> active bit
// ---------------------------------------------------------------------------
__global__ void cls_head_kernel(const float* __restrict__ lnw,
                                const float* __restrict__ lnb,
                                const float* __restrict__ w2,
                                const float* __restrict__ b2) {
    int d = blockIdx.x;
    int b = blockIdx.y;
    int t = threadIdx.x;   // 128
    __shared__ float red[128];
    const float* row = g_h1 + ((long)(d * B + b)) * H2;

    float s = 0.f;
    for (int i = t; i < H2; i += 128) s += row[i];
    red[t] = s; __syncthreads();
    for (int o = 64; o > 0; o >>= 1) { if (t < o) red[t] += red[t + o]; __syncthreads(); }
    float mu = red[0] / H2;
    __syncthreads();

    float vs = 0.f;
    for (int i = t; i < H2; i += 128) { float dd = row[i] - mu; vs += dd * dd; }
    red[t] = vs; __syncthreads();
    for (int o = 64; o > 0; o >>= 1) { if (t < o) red[t] += red[t + o]; __syncthreads(); }
    float var = red[0] / H2;
    float rs = rsqrtf(var + 1e-5f);
    __syncthreads();

    float dot = 0.f;
    for (int i = t; i < H2; i += 128) {
        float v = (row[i] - mu) * rs * lnw[d * H2 + i] + lnb[d * H2 + i];
        v = gelu_exact(v);
        dot += v * w2[d * H2 + i];
    }
    red[t] = dot; __syncthreads();
    for (int o = 64; o > 0; o >>= 1) { if (t < o) red[t] += red[t + o]; __syncthreads(); }
    if (t == 0) {
        float pred = red[0] + b2[d];
        g_act[b * D + d] = (g_cnt[d] > 0.f && pred > 0.f) ? 1.f : 0.f;
    }
}

// ---------------------------------------------------------------------------
// expert weights w[b,s,e]
// ---------------------------------------------------------------------------
__global__ void w_kernel(const float* __restrict__ mask) {
    int idx = blockIdx.x * blockDim.x + threadIdx.x;
    if (idx >= MROWS) return;
    int s = idx % S;
    int b = idx / S;
    float a[E];
    float sum = 1.f;
    for (int d = 0; d < D; d++) {
        float v = 0.f;
        if (s > 0 && mask[(s - 1) * D + d] > 0.f) v = g_act[b * D + d];
        a[d] = v;
        sum += v;
    }
    a[D] = 1.f;
    float inv = 1.f / sum;
    for (int e = 0; e < E; e++) g_w[idx * E + e] = a[e] * inv;
}

// ---------------------------------------------------------------------------
// M[e,r,r'] = sum_f A_down[e,r,f] * B_up[e,f,r']
// ---------------------------------------------------------------------------
__global__ void mmat_kernel(const float* __restrict__ Adown,
                            const float* __restrict__ Bup) {
    int e  = blockIdx.x >> 6;
    int p  = blockIdx.x & 63;
    int r  = p >> 3;
    int rp = p & 7;
    int t = threadIdx.x;   // 128
    __shared__ float red[128];
    const float* ad = Adown + ((long)e * RK + r) * FF;
    const float* bu = Bup + (long)e * FF * RK + rp;
    float s = 0.f;
    for (int f = t; f < FF; f += 128) s += ad[f] * bu[(long)f * RK];
    red[t] = s; __syncthreads();
    for (int o = 64; o > 0; o >>= 1) { if (t < o) red[t] += red[t + o]; __syncthreads(); }
    if (t == 0) g_M[e * 64 + p] = red[0];
}

// ---------------------------------------------------------------------------
// a_dn = G + SCALING * M @ a_up
// ---------------------------------------------------------------------------
__global__ void adn_kernel() {
    int idx = blockIdx.x * 256 + threadIdx.x;
    if (idx >= MROWS * E * RK) return;
    int c = idx % (E * RK);
    int m = idx / (E * RK);
    int e = c / RK, r = c % RK;
    float s = g_G[idx];
    const float* mrow = g_M + e * 64 + r * 8;
    const float* au = g_aup + (long)m * (E * RK) + e * RK;
#pragma unroll
    for (int rp = 0; rp < 8; rp++) s += SCALING * mrow[rp] * au[rp];
    g_adn[idx] = s;
}

// ---------------------------------------------------------------------------
// Mixture epilogue
// ---------------------------------------------------------------------------
__global__ void mix_kernel(const float* __restrict__ Bdown) {
    int m = blockIdx.x;
    int t = threadIdx.x;   // 256
    __shared__ float wsh[E];
    __shared__ float adn[E * RK];
    __shared__ float bos[H];
    __shared__ float red[256];

    if (t < E) wsh[t] = g_w[m * E + t];
    if (t < E * RK) adn[t] = g_adn[(long)m * (E * RK) + t];
    for (int i = t; i < H; i += 256) bos[i] = g_bo[(long)m * H + i];
    __syncthreads();

    float acc[3] = {0.f, 0.f, 0.f};

    for (int e = 0; e < E; e++) {
        float we = wsh[e];
        if (we == 0.f) continue;
        float v[3];
        float ssum = 0.f;
#pragma unroll
        for (int i = 0; i < 3; i++) {
            int h = t + i * 256;
            const float* bd = Bdown + ((long)e * H + h) * RK;
            float l = 0.f;
#pragma unroll
            for (int r2 = 0; r2 < 8; r2++) l += bd[r2] * adn[e * RK + r2];
            v[i] = bos[h] + SCALING * l;
            ssum += v[i];
        }
        red[t] = ssum; __syncthreads();
        for (int o = 128; o > 0; o >>= 1) { if (t < o) red[t] += red[t + o]; __syncthreads(); }
        float mu = red[0] * (1.0f / H);
        __syncthreads();

        float vsum = 0.f;
#pragma unroll
        for (int i = 0; i < 3; i++) { float dd = v[i] - mu; vsum += dd * dd; }
        red[t] = vsum; __syncthreads();
        for (int o = 128; o > 0; o >>= 1) { if (t < o) red[t] += red[t + o]; __syncthreads(); }
        float var = red[0] * (1.0f / H);
        __syncthreads();
        float rs = rsqrtf(var + 1e-5f);
#pragma unroll
        for (int i = 0; i < 3; i++) acc[i] += we * (v[i] - mu) * rs;
    }

#pragma unroll
    for (int i = 0; i < 3; i++) {
        int h = t + i * 256;
        g_hs[(long)m * H + h] = acc[i] + g_res1[(long)m * H + h];
    }
}

// ---------------------------------------------------------------------------
// Host side
// ---------------------------------------------------------------------------
static void launch_gemm(const float* A, const float* W, const float* bias,
                        const float* res, float* C, int M, int N, int K,
                        int do_gelu, int batch = 1,
                        long sA = 0, long sW = 0, long sB = 0, long sC = 0) {
    if (N >= 1536) {
        dim3 grid((N + 63) / 64, (M + 63) / 64, batch);
        mma_gemm_kernel<64><<<grid, 128>>>(A, W, bias, res, C, M, N, K,
                                           sA, sW, sB, sC, do_gelu);
    } else {
        dim3 grid((N + 31) / 32, (M + 63) / 64, batch);
        mma_gemm_kernel<32><<<grid, 128>>>(A, W, bias, res, C, M, N, K,
                                           sA, sW, sB, sC, do_gelu);
    }
}

extern "C" void kernel_launch(void* const* d_in, const int* in_sizes, int n_in,
                              void* d_out, int out_size) {
    const float* region = (const float*)d_in[0];
    const float* mask   = (const float*)d_in[1];
    const float* cls    = (const float*)d_in[2];
    const float* ln1w   = (const float*)d_in[3];
    const float* ln1b   = (const float*)d_in[4];
    const float* qkvw   = (const float*)d_in[5];
    const float* qkvb   = (const float*)d_in[6];
    const float* aow    = (const float*)d_in[7];
    const float* aob    = (const float*)d_in[8];
    const float* ln2w   = (const float*)d_in[9];
    const float* ln2b   = (const float*)d_in[10];
    const float* fw1    = (const float*)d_in[11];
    const float* fb1    = (const float*)d_in[12];
    const float* fw2    = (const float*)d_in[13];
    const float* fb2    = (const float*)d_in[14];
    const float* cw1    = (const float*)d_in[15];
    const float* cb1    = (const float*)d_in[16];
    const float* clnw   = (const float*)d_in[17];
    const float* clnb   = (const float*)d_in[18];
    const float* cw2    = (const float*)d_in[19];
    const float* cb2    = (const float*)d_in[20];
    const float* lAu    = (const float*)d_in[21];
    const float* lBu    = (const float*)d_in[22];
    const float* lAd    = (const float*)d_in[23];
    const float* lBd    = (const float*)d_in[24];
    const float* flw    = (const float*)d_in[25];
    const float* flb    = (const float*)d_in[26];
    float* out = (float*)d_out;

    float *hs, *xln, *qkv, *ctx, *res1, *y, *bh, *bo, *pooled, *h1, *aup, *G;
    cudaGetSymbolAddress((void**)&hs,   g_hs);
    cudaGetSymbolAddress((void**)&xln,  g_xln);
    cudaGetSymbolAddress((void**)&qkv,  g_qkv);
    cudaGetSymbolAddress((void**)&ctx,  g_ctx);
    cudaGetSymbolAddress((void**)&res1, g_res1);
    cudaGetSymbolAddress((void**)&y,    g_y);
    cudaGetSymbolAddress((void**)&bh,   g_bh);
    cudaGetSymbolAddress((void**)&bo,   g_bo);
    cudaGetSymbolAddress((void**)&pooled, g_pooled);
    cudaGetSymbolAddress((void**)&h1,   g_h1);
    cudaGetSymbolAddress((void**)&aup,  g_aup);
    cudaGetSymbolAddress((void**)&G,    g_G);

    const int NE = MROWS * H;   // 737280

    init_hs_kernel<<<(NE + 255) / 256, 256>>>(region, cls);

    for (int i = 0; i < L; i++) {
        const int j = i / 2;

        // x_ln = LN(hs, ln1)
        ln_kernel<<<MROWS, 256>>>(hs, ln1w + (long)i * H, ln1b + (long)i * H, xln, H, 1e-12f);

        // qkv = x_ln @ qkv_w[i]^T + qkv_b[i]
        launch_gemm(xln, qkvw + (long)i * 3 * H * H, qkvb + (long)i * 3 * H,
                    nullptr, qkv, MROWS, 3 * H, H, 0);

        // attention -> ctx
        attn_kernel<<<dim3(B, NH), 256>>>();

        // res1 = ctx @ ow^T + ob + hs   (residual fused into epilogue)
        launch_gemm(ctx, aow + (long)i * H * H, aob + (long)i * H,
                    hs, res1, MROWS, H, H, 0);

        // y = LN(res1, ln2)
        ln_kernel<<<MROWS, 256>>>(res1, ln2w + (long)i * H, ln2b + (long)i * H, y, H, 1e-12f);

        // base_hidden = gelu(y @ w1^T + b1)
        launch_gemm(y, fw1 + (long)i * FF * H, fb1 + (long)i * FF,
                    nullptr, bh, MROWS, FF, H, 1);

        if (i % 2 == 1) {
            // hs = base_hidden @ w2^T + b2 + res1
            launch_gemm(bh, fw2 + (long)i * H * FF, fb2 + (long)i * H,
                        res1, hs, MROWS, H, FF, 0);
        } else {
            // base_out (no residual)
            launch_gemm(bh, fw2 + (long)i * H * FF, fb2 + (long)i * H,
                        nullptr, bo, MROWS, H, FF, 0);

            // ---- classifier ----
            pool_kernel<<<dim3(D, B), 256>>>(mask);
            launch_gemm(pooled, cw1 + (long)j * D * H2 * H, cb1 + (long)j * D * H2,
                        nullptr, h1, B, H2, H, 0,
                        D, (long)B * H, (long)H2 * H, (long)H2, (long)B * H2);
            cls_head_kernel<<<dim3(D, B), 128>>>(clnw + (long)j * D * H2,
                                                 clnb + (long)j * D * H2,
                                                 cw2 + (long)j * D * H2,
                                                 cb2 + (long)j * D);
            w_kernel<<<(MROWS + 127) / 128, 128>>>(mask);

            // ---- LoRA (factored, no (b,s,e,FF) tensor) ----
            launch_gemm(y, lAu + (long)j * E * RK * H, nullptr,
                        nullptr, aup, MROWS, E * RK, H, 0);
            launch_gemm(bh, lAd + (long)j * E * RK * FF, nullptr,
                        nullptr, G, MROWS, E * RK, FF, 0);
            mmat_kernel<<<E * 64, 128>>>(lAd + (long)j * E * RK * FF,
                                         lBu + (long)j * E * FF * RK);
            adn_kernel<<<(MROWS * E * RK + 255) / 256, 256>>>();
            mix_kernel<<<MROWS, 256>>>(lBd + (long)j * E * H * RK);
        }
    }

    // final layernorm -> output
    ln_kernel<<<MROWS, 256>>>(hs, flw, flb, out, H, 1e-12f);
}

// round 4
// speedup vs baseline: 3.0114x; 1.2516x over previous
#include <cuda_runtime.h>
#include <cuda_bf16.h>
#include <math.h>
#include <stdint.h>

// ---------------------------------------------------------------------------
// Problem constants
// ---------------------------------------------------------------------------
namespace {
constexpr int B = 32, R = 29, S = 30, H = 768, NH = 12, DH = 64, FF = 3072;
constexpr int L = 12, D = 14, E = 15, RK = 8, H2 = 384;
constexpr int MROWS = B * S;          // 960
constexpr float SCALING = 2.0f;       // 16/8
}

// ---------------------------------------------------------------------------
// Global scratch (fp32)
// ---------------------------------------------------------------------------
__device__ float g_hs  [MROWS * H];
__device__ float g_qkv [MROWS * 3 * H];
__device__ float g_res1[MROWS * H];
__device__ float g_bo  [MROWS * H];
__device__ float g_h1  [D * B * H2];
__device__ float g_act [B * D];
__device__ float g_cnt [D];
__device__ float g_aup [MROWS * E * RK];
__device__ float g_G   [MROWS * E * RK];
__device__ float g_adn [MROWS * E * RK];
__device__ float g_M   [E * RK * RK];
__device__ float g_w   [MROWS * E];

// ---------------------------------------------------------------------------
// bf16 hi/lo planes: activations
// ---------------------------------------------------------------------------
__device__ __nv_bfloat16 g_xln_h[MROWS * H],  g_xln_l[MROWS * H];
__device__ __nv_bfloat16 g_y_h  [MROWS * H],  g_y_l  [MROWS * H];
__device__ __nv_bfloat16 g_ctx_h[MROWS * H],  g_ctx_l[MROWS * H];
__device__ __nv_bfloat16 g_bh_h [MROWS * FF], g_bh_l [MROWS * FF];
__device__ __nv_bfloat16 g_pool_h[D * B * H], g_pool_l[D * B * H];

// ---------------------------------------------------------------------------
// bf16 hi/lo planes: weights (split once per launch)
// ---------------------------------------------------------------------------
__device__ __nv_bfloat16 g_qkvw_h[L * 3 * H * H], g_qkvw_l[L * 3 * H * H];
__device__ __nv_bfloat16 g_aow_h [L * H * H],     g_aow_l [L * H * H];
__device__ __nv_bfloat16 g_fw1_h [L * FF * H],    g_fw1_l [L * FF * H];
__device__ __nv_bfloat16 g_fw2_h [L * H * FF],    g_fw2_l [L * H * FF];
__device__ __nv_bfloat16 g_cw1_h [(L/2) * D * H2 * H], g_cw1_l[(L/2) * D * H2 * H];
__device__ __nv_bfloat16 g_lAu_h [(L/2) * E * RK * H],  g_lAu_l[(L/2) * E * RK * H];
__device__ __nv_bfloat16 g_lAd_h [(L/2) * E * RK * FF], g_lAd_l[(L/2) * E * RK * FF];

// ---------------------------------------------------------------------------
// Helpers
// ---------------------------------------------------------------------------
__device__ __forceinline__ float gelu_exact(float v) {
    return 0.5f * v * (1.0f + erff(v * 0.70710678118654752f));
}

__device__ __forceinline__ void split_one(float v, __nv_bfloat16& hi, __nv_bfloat16& lo) {
    hi = __float2bfloat16(v);
    lo = __float2bfloat16(v - __bfloat162float(hi));
}

__device__ __forceinline__ void mma16816(float c[4], const uint32_t a[4],
                                         uint32_t b0, uint32_t b1) {
    asm volatile(
        "mma.sync.aligned.m16n8k16.row.col.f32.bf16.bf16.f32 "
        "{%0,%1,%2,%3}, {%4,%5,%6,%7}, {%8,%9}, {%0,%1,%2,%3};\n"
        : "+f"(c[0]), "+f"(c[1]), "+f"(c[2]), "+f"(c[3])
        : "r"(a[0]), "r"(a[1]), "r"(a[2]), "r"(a[3]), "r"(b0), "r"(b1));
}

__device__ __forceinline__ void ldsm4(uint32_t (&r)[4], uint32_t addr) {
    asm volatile("ldmatrix.sync.aligned.m8n8.x4.shared.b16 {%0,%1,%2,%3}, [%4];"
                 : "=r"(r[0]), "=r"(r[1]), "=r"(r[2]), "=r"(r[3]) : "r"(addr));
}

__device__ __forceinline__ void cp16(uint32_t dst, const void* src, bool valid) {
    int sz = valid ? 16 : 0;
    asm volatile("cp.async.cg.shared.global [%0], [%1], 16, %2;"
                 :: "r"(dst), "l"(src), "r"(sz));
}

// ---------------------------------------------------------------------------
// fp32 -> hi/lo split kernel (weights, once per launch)
// ---------------------------------------------------------------------------
__global__ void split_kernel(const float* __restrict__ src,
                             __nv_bfloat16* __restrict__ hi,
                             __nv_bfloat16* __restrict__ lo, int n4) {
    int i = blockIdx.x * blockDim.x + threadIdx.x;
    if (i >= n4) return;
    float4 v = reinterpret_cast<const float4*>(src)[i];
    __nv_bfloat16 h[4], l[4];
    split_one(v.x, h[0], l[0]); split_one(v.y, h[1], l[1]);
    split_one(v.z, h[2], l[2]); split_one(v.w, h[3], l[3]);
    __nv_bfloat162* h2 = reinterpret_cast<__nv_bfloat162*>(hi);
    __nv_bfloat162* l2 = reinterpret_cast<__nv_bfloat162*>(lo);
    h2[2 * i]     = __nv_bfloat162(h[0], h[1]);
    h2[2 * i + 1] = __nv_bfloat162(h[2], h[3]);
    l2[2 * i]     = __nv_bfloat162(l[0], l[1]);
    l2[2 * i + 1] = __nv_bfloat162(l[2], l[3]);
}

// ---------------------------------------------------------------------------
// hs init
// ---------------------------------------------------------------------------
__global__ void init_hs_kernel(const float* __restrict__ region,
                               const float* __restrict__ cls) {
    int idx = blockIdx.x * blockDim.x + threadIdx.x;
    if (idx >= MROWS * H) return;
    int h = idx % H;
    int m = idx / H;
    int s = m % S;
    int b = m / S;
    g_hs[idx] = (s == 0) ? cls[h] : region[((long)b * R + (s - 1)) * H + h];
}

// ---------------------------------------------------------------------------
// LayerNorm writing fp32 (final) or hi/lo planes
// ---------------------------------------------------------------------------
__global__ void ln_kernel(const float* __restrict__ x,
                          const float* __restrict__ w,
                          const float* __restrict__ b,
                          float* __restrict__ out, float eps) {
    int row = blockIdx.x;
    int t = threadIdx.x;
    const float* xr = x + (long)row * H;
    __shared__ float red[256];

    float s = 0.f;
    for (int i = t; i < H; i += 256) s += xr[i];
    red[t] = s; __syncthreads();
    for (int o = 128; o > 0; o >>= 1) { if (t < o) red[t] += red[t + o]; __syncthreads(); }
    float mu = red[0] / H;
    __syncthreads();
    float vs = 0.f;
    for (int i = t; i < H; i += 256) { float d = xr[i] - mu; vs += d * d; }
    red[t] = vs; __syncthreads();
    for (int o = 128; o > 0; o >>= 1) { if (t < o) red[t] += red[t + o]; __syncthreads(); }
    float rs = rsqrtf(red[0] / H + eps);
    for (int i = t; i < H; i += 256)
        out[(long)row * H + i] = (xr[i] - mu) * rs * w[i] + b[i];
}

__global__ void ln_planes_kernel(const float* __restrict__ x,
                                 const float* __restrict__ w,
                                 const float* __restrict__ b,
                                 __nv_bfloat16* __restrict__ ohi,
                                 __nv_bfloat16* __restrict__ olo, float eps) {
    int row = blockIdx.x;
    int t = threadIdx.x;
    const float* xr = x + (long)row * H;
    __shared__ float red[256];

    float s = 0.f;
    for (int i = t; i < H; i += 256) s += xr[i];
    red[t] = s; __syncthreads();
    for (int o = 128; o > 0; o >>= 1) { if (t < o) red[t] += red[t + o]; __syncthreads(); }
    float mu = red[0] / H;
    __syncthreads();
    float vs = 0.f;
    for (int i = t; i < H; i += 256) { float d = xr[i] - mu; vs += d * d; }
    red[t] = vs; __syncthreads();
    for (int o = 128; o > 0; o >>= 1) { if (t < o) red[t] += red[t + o]; __syncthreads(); }
    float rs = rsqrtf(red[0] / H + eps);
    for (int i = t; i < H; i += 256) {
        float v = (xr[i] - mu) * rs * w[i] + b[i];
        __nv_bfloat16 hi, lo;
        split_one(v, hi, lo);
        ohi[(long)row * H + i] = hi;
        olo[(long)row * H + i] = lo;
    }
}

// ---------------------------------------------------------------------------
// Tensor-core GEMM v3: bf16 hi/lo planes in, cp.async double buffer, ldmatrix.
// C[m,n] = epi( sum_k A[m,k]*W[n,k] + bias[n] )(+res) [+plane out]
// Block tile BM x 64 x 32, 256 threads. K % 32 == 0.
// ---------------------------------------------------------------------------
template<int BM, int NT>
__global__ __launch_bounds__(256)
void mma_gemm_v3(const __nv_bfloat16* __restrict__ Ah, const __nv_bfloat16* __restrict__ Al,
                 const __nv_bfloat16* __restrict__ Wh, const __nv_bfloat16* __restrict__ Wl,
                 const float* __restrict__ bias, const float* __restrict__ res,
                 float* __restrict__ C,
                 __nv_bfloat16* __restrict__ Chi, __nv_bfloat16* __restrict__ Clo,
                 int Mm, int Nn, int Kk,
                 long sA, long sW, long sB, long sC, int do_gelu) {
    constexpr int WARPS_M = BM / 32;
    constexpr int STG_BYTES = (2 * BM + 128) * 80;   // per stage
    constexpr int ACH = BM * 4;                      // A chunks per plane
    constexpr int CHUNKS = 2 * ACH + 512;
    constexpr int NLOAD = CHUNKS / 256;
    constexpr int NT2 = NT / 2;

    extern __shared__ char dynsmem[];
    const uint32_t sbase = (uint32_t)__cvta_generic_to_shared(dynsmem);

    int z = blockIdx.z;
    Ah += (long)z * sA;  Al += (long)z * sA;
    Wh += (long)z * sW;  Wl += (long)z * sW;
    if (bias) bias += (long)z * sB;
    if (res)  res  += (long)z * sC;
    if (C)    C    += (long)z * sC;
    if (Chi) { Chi += (long)z * sC; Clo += (long)z * sC; }

    const int t = threadIdx.x;
    const int w = t >> 5;
    const int lane = t & 31;
    const int wm = (w % WARPS_M) * 32;
    const int wn = (w / WARPS_M) * (NT * 8);
    const int m0 = blockIdx.y * BM;
    const int n0 = blockIdx.x * 64;

    // per-thread ldmatrix address components (bytes)
    const int a_row = lane & 15;
    const int a_col = lane >> 4;
    const int b_row = (lane & 7) + ((lane >> 3) & 1) * 8;
    const int b_col = lane >> 4;

    float acc[2][NT][4];
#pragma unroll
    for (int i = 0; i < 2; i++)
#pragma unroll
        for (int j = 0; j < NT; j++)
#pragma unroll
            for (int q = 0; q < 4; q++) acc[i][j][q] = 0.f;

    // ---- async load of one stage ----
    auto load_stage = [&](int stg, int k0) {
        const uint32_t base = sbase + stg * STG_BYTES;
#pragma unroll
        for (int i = 0; i < NLOAD; i++) {
            int c = t + i * 256;
            const __nv_bfloat16* src;
            uint32_t dst;
            bool ok;
            if (c < ACH) {
                int row = c >> 2, kc = c & 3;
                ok = (m0 + row) < Mm;
                src = Ah + (long)(m0 + row) * Kk + k0 + kc * 8;
                dst = base + row * 80 + kc * 16;
            } else if (c < 2 * ACH) {
                int c2 = c - ACH;
                int row = c2 >> 2, kc = c2 & 3;
                ok = (m0 + row) < Mm;
                src = Al + (long)(m0 + row) * Kk + k0 + kc * 8;
                dst = base + BM * 80 + row * 80 + kc * 16;
            } else if (c < 2 * ACH + 256) {
                int c2 = c - 2 * ACH;
                int row = c2 >> 2, kc = c2 & 3;
                ok = (n0 + row) < Nn;
                src = Wh + (long)(n0 + row) * Kk + k0 + kc * 8;
                dst = base + 2 * BM * 80 + row * 80 + kc * 16;
            } else {
                int c2 = c - 2 * ACH - 256;
                int row = c2 >> 2, kc = c2 & 3;
                ok = (n0 + row) < Nn;
                src = Wl + (long)(n0 + row) * Kk + k0 + kc * 8;
                dst = base + 2 * BM * 80 + 5120 + row * 80 + kc * 16;
            }
            cp16(dst, src, ok);
        }
    };

    const int niter = Kk / 32;
    load_stage(0, 0);
    asm volatile("cp.async.commit_group;");

    for (int it = 0; it < niter; it++) {
        if (it + 1 < niter) load_stage((it + 1) & 1, (it + 1) * 32);
        asm volatile("cp.async.commit_group;");
        asm volatile("cp.async.wait_group 1;");
        __syncthreads();

        const uint32_t base = sbase + (it & 1) * STG_BYTES;
#pragma unroll
        for (int kk = 0; kk < 2; kk++) {
            const int kb = kk * 32;
            uint32_t ah[2][4], al[2][4], bh[NT2][4], bl[NT2][4];
#pragma unroll
            for (int mt = 0; mt < 2; mt++) {
                uint32_t ab = base + (wm + mt * 16 + a_row) * 80 + a_col * 16 + kb;
                ldsm4(ah[mt], ab);
                ldsm4(al[mt], ab + BM * 80);
            }
#pragma unroll
            for (int nt2 = 0; nt2 < NT2; nt2++) {
                uint32_t bb = base + 2 * BM * 80 + (wn + nt2 * 16 + b_row) * 80 + b_col * 16 + kb;
                ldsm4(bh[nt2], bb);
                ldsm4(bl[nt2], bb + 5120);
            }
#pragma unroll
            for (int nt = 0; nt < NT; nt++) {
                int n2 = nt >> 1, sel = nt & 1;
                uint32_t b0h = bh[n2][sel], b1h = bh[n2][2 + sel];
                uint32_t b0l = bl[n2][sel], b1l = bl[n2][2 + sel];
#pragma unroll
                for (int mt = 0; mt < 2; mt++) {
                    mma16816(acc[mt][nt], ah[mt], b0h, b1h);
                    mma16816(acc[mt][nt], ah[mt], b0l, b1l);
                    mma16816(acc[mt][nt], al[mt], b0h, b1h);
                }
            }
        }
        __syncthreads();
    }

    // ---- epilogue ----
    const int grp = lane >> 2;
    const int tid4 = lane & 3;
#pragma unroll
    for (int mt = 0; mt < 2; mt++) {
#pragma unroll
        for (int nt = 0; nt < NT; nt++) {
#pragma unroll
            for (int half = 0; half < 2; half++) {
                int row = m0 + wm + mt * 16 + grp + half * 8;
                if (row >= Mm) continue;
#pragma unroll
                for (int q = 0; q < 2; q++) {
                    int col = n0 + wn + nt * 8 + tid4 * 2 + q;
                    if (col >= Nn) continue;
                    float v = acc[mt][nt][half * 2 + q];
                    if (bias) v += bias[col];
                    if (do_gelu) v = gelu_exact(v);
                    if (res) v += res[(long)row * Nn + col];
                    long o = (long)row * Nn + col;
                    if (C) C[o] = v;
                    if (Chi) {
                        __nv_bfloat16 hi, lo;
                        split_one(v, hi, lo);
                        Chi[o] = hi; Clo[o] = lo;
                    }
                }
            }
        }
    }
}

// ---------------------------------------------------------------------------
// Attention: one block per (batch, head). Writes ctx hi/lo planes.
// ---------------------------------------------------------------------------
__global__ void attn_kernel() {
    int b = blockIdx.x;
    int n = blockIdx.y;
    __shared__ float q[S][DH], k[S][DH], v[S][DH];
    __shared__ float sc[S][S + 2];
    int t = threadIdx.x;   // 256

    for (int i = t; i < S * DH; i += 256) {
        int s = i / DH, d = i % DH;
        long base = ((long)(b * S + s)) * (3 * H) + n * DH + d;
        q[s][d] = g_qkv[base];
        k[s][d] = g_qkv[base + H];
        v[s][d] = g_qkv[base + 2 * H];
    }
    __syncthreads();

    for (int p = t; p < S * S; p += 256) {
        int qi = p / S, ki = p % S;
        float s = 0.f;
#pragma unroll
        for (int d = 0; d < DH; d++) s += q[qi][d] * k[ki][d];
        sc[qi][ki] = s * 0.125f;
    }
    __syncthreads();

    if (t < S) {
        float mx = -1e30f;
        for (int ki = 0; ki < S; ki++) mx = fmaxf(mx, sc[t][ki]);
        float sum = 0.f;
        for (int ki = 0; ki < S; ki++) { float e = __expf(sc[t][ki] - mx); sc[t][ki] = e; sum += e; }
        float inv = 1.f / sum;
        for (int ki = 0; ki < S; ki++) sc[t][ki] *= inv;
    }
    __syncthreads();

    for (int p = t; p < S * DH; p += 256) {
        int qi = p / DH, d = p % DH;
        float s = 0.f;
#pragma unroll
        for (int ki = 0; ki < S; ki++) s += sc[qi][ki] * v[ki][d];
        long o = ((long)(b * S + qi)) * H + n * DH + d;
        __nv_bfloat16 hi, lo;
        split_one(s, hi, lo);
        g_ctx_h[o] = hi; g_ctx_l[o] = lo;
    }
}

// ---------------------------------------------------------------------------
// pooled planes from (res1 - hs) region rows
// ---------------------------------------------------------------------------
__global__ void pool_kernel(const float* __restrict__ mask) {
    int d = blockIdx.x;
    int b = blockIdx.y;
    int t = threadIdx.x;   // 256
    __shared__ float mk[R];
    __shared__ float inv;
    if (t < R) mk[t] = mask[t * D + d];
    __syncthreads();
    if (t == 0) {
        float c = 0.f;
        for (int r = 0; r < R; r++) c += mk[r];
        if (b == 0) g_cnt[d] = c;
        inv = 1.f / fmaxf(c, 1.f);
    }
    __syncthreads();
    for (int h = t; h < H; h += 256) {
        float s = 0.f;
#pragma unroll 1
        for (int r = 0; r < R; r++) {
            long idx = ((long)(b * S + 1 + r)) * H + h;
            s += (g_res1[idx] - g_hs[idx]) * mk[r];
        }
        long o = ((long)(d * B + b)) * H + h;
        __nv_bfloat16 hi, lo;
        split_one(s * inv, hi, lo);
        g_pool_h[o] = hi; g_pool_l[o] = lo;
    }
}

// ---------------------------------------------------------------------------
// classifier head: LN(1e-5) + gelu + dot(w2) + b2 -> active bit
// ---------------------------------------------------------------------------
__global__ void cls_head_kernel(const float* __restrict__ lnw,
                                const float* __restrict__ lnb,
                                const float* __restrict__ w2,
                                const float* __restrict__ b2) {
    int d = blockIdx.x;
    int b = blockIdx.y;
    int t = threadIdx.x;   // 128
    __shared__ float red[128];
    const float* row = g_h1 + ((long)(d * B + b)) * H2;

    float s = 0.f;
    for (int i = t; i < H2; i += 128) s += row[i];
    red[t] = s; __syncthreads();
    for (int o = 64; o > 0; o >>= 1) { if (t < o) red[t] += red[t + o]; __syncthreads(); }
    float mu = red[0] / H2;
    __syncthreads();
    float vs = 0.f;
    for (int i = t; i < H2; i += 128) { float dd = row[i] - mu; vs += dd * dd; }
    red[t] = vs; __syncthreads();
    for (int o = 64; o > 0; o >>= 1) { if (t < o) red[t] += red[t + o]; __syncthreads(); }
    float rs = rsqrtf(red[0] / H2 + 1e-5f);
    __syncthreads();

    float dot = 0.f;
    for (int i = t; i < H2; i += 128) {
        float v = (row[i] - mu) * rs * lnw[d * H2 + i] + lnb[d * H2 + i];
        v = gelu_exact(v);
        dot += v * w2[d * H2 + i];
    }
    red[t] = dot; __syncthreads();
    for (int o = 64; o > 0; o >>= 1) { if (t < o) red[t] += red[t + o]; __syncthreads(); }
    if (t == 0) {
        float pred = red[0] + b2[d];
        g_act[b * D + d] = (g_cnt[d] > 0.f && pred > 0.f) ? 1.f : 0.f;
    }
}

// ---------------------------------------------------------------------------
// expert weights
// ---------------------------------------------------------------------------
__global__ void w_kernel(const float* __restrict__ mask) {
    int idx = blockIdx.x * blockDim.x + threadIdx.x;
    if (idx >= MROWS) return;
    int s = idx % S;
    int b = idx / S;
    float a[E];
    float sum = 1.f;
    for (int d = 0; d < D; d++) {
        float v = 0.f;
        if (s > 0 && mask[(s - 1) * D + d] > 0.f) v = g_act[b * D + d];
        a[d] = v;
        sum += v;
    }
    a[D] = 1.f;
    float inv = 1.f / sum;
    for (int e = 0; e < E; e++) g_w[idx * E + e] = a[e] * inv;
}

// ---------------------------------------------------------------------------
// M[e,r,r'] = sum_f A_down[e,r,f] * B_up[e,f,r']
// ---------------------------------------------------------------------------
__global__ void mmat_kernel(const float* __restrict__ Adown,
                            const float* __restrict__ Bup) {
    int e  = blockIdx.x >> 6;
    int p  = blockIdx.x & 63;
    int r  = p >> 3;
    int rp = p & 7;
    int t = threadIdx.x;   // 128
    __shared__ float red[128];
    const float* ad = Adown + ((long)e * RK + r) * FF;
    const float* bu = Bup + (long)e * FF * RK + rp;
    float s = 0.f;
    for (int f = t; f < FF; f += 128) s += ad[f] * bu[(long)f * RK];
    red[t] = s; __syncthreads();
    for (int o = 64; o > 0; o >>= 1) { if (t < o) red[t] += red[t + o]; __syncthreads(); }
    if (t == 0) g_M[e * 64 + p] = red[0];
}

// ---------------------------------------------------------------------------
// a_dn = G + SCALING * M @ a_up
// ---------------------------------------------------------------------------
__global__ void adn_kernel() {
    int idx = blockIdx.x * 256 + threadIdx.x;
    if (idx >= MROWS * E * RK) return;
    int c = idx % (E * RK);
    int m = idx / (E * RK);
    int e = c / RK, r = c % RK;
    float s = g_G[idx];
    const float* mrow = g_M + e * 64 + r * 8;
    const float* au = g_aup + (long)m * (E * RK) + e * RK;
#pragma unroll
    for (int rp = 0; rp < 8; rp++) s += SCALING * mrow[rp] * au[rp];
    g_adn[idx] = s;
}

// ---------------------------------------------------------------------------
// Mixture epilogue
// ---------------------------------------------------------------------------
__global__ void mix_kernel(const float* __restrict__ Bdown) {
    int m = blockIdx.x;
    int t = threadIdx.x;   // 256
    __shared__ float wsh[E];
    __shared__ float adn[E * RK];
    __shared__ float bos[H];
    __shared__ float red[256];

    if (t < E) wsh[t] = g_w[m * E + t];
    if (t < E * RK) adn[t] = g_adn[(long)m * (E * RK) + t];
    for (int i = t; i < H; i += 256) bos[i] = g_bo[(long)m * H + i];
    __syncthreads();

    float acc[3] = {0.f, 0.f, 0.f};

    for (int e = 0; e < E; e++) {
        float we = wsh[e];
        if (we == 0.f) continue;
        float v[3];
        float ssum = 0.f;
#pragma unroll
        for (int i = 0; i < 3; i++) {
            int h = t + i * 256;
            const float* bd = Bdown + ((long)e * H + h) * RK;
            float l = 0.f;
#pragma unroll
            for (int r2 = 0; r2 < 8; r2++) l += bd[r2] * adn[e * RK + r2];
            v[i] = bos[h] + SCALING * l;
            ssum += v[i];
        }
        red[t] = ssum; __syncthreads();
        for (int o = 128; o > 0; o >>= 1) { if (t < o) red[t] += red[t + o]; __syncthreads(); }
        float mu = red[0] * (1.0f / H);
        __syncthreads();

        float vsum = 0.f;
#pragma unroll
        for (int i = 0; i < 3; i++) { float dd = v[i] - mu; vsum += dd * dd; }
        red[t] = vsum; __syncthreads();
        for (int o = 128; o > 0; o >>= 1) { if (t < o) red[t] += red[t + o]; __syncthreads(); }
        float var = red[0] * (1.0f / H);
        __syncthreads();
        float rs = rsqrtf(var + 1e-5f);
#pragma unroll
        for (int i = 0; i < 3; i++) acc[i] += we * (v[i] - mu) * rs;
    }

#pragma unroll
    for (int i = 0; i < 3; i++) {
        int h = t + i * 256;
        g_hs[(long)m * H + h] = acc[i] + g_res1[(long)m * H + h];
    }
}

// ---------------------------------------------------------------------------
// Host side
// ---------------------------------------------------------------------------
static void launch_gemm3(const __nv_bfloat16* Ah, const __nv_bfloat16* Al,
                         const __nv_bfloat16* Wh, const __nv_bfloat16* Wl,
                         const float* bias, const float* res,
                         float* C, __nv_bfloat16* Chi, __nv_bfloat16* Clo,
                         int M, int N, int K, int do_gelu, int batch = 1,
                         long sA = 0, long sW = 0, long sB = 0, long sC = 0) {
    if (N >= 1536) {
        dim3 grid((N + 63) / 64, (M + 127) / 128, batch);
        mma_gemm_v3<128, 4><<<grid, 256, 61440>>>(Ah, Al, Wh, Wl, bias, res, C,
                                                  Chi, Clo, M, N, K, sA, sW, sB, sC, do_gelu);
    } else {
        dim3 grid((N + 63) / 64, (M + 63) / 64, batch);
        mma_gemm_v3<64, 2><<<grid, 256, 40960>>>(Ah, Al, Wh, Wl, bias, res, C,
                                                 Chi, Clo, M, N, K, sA, sW, sB, sC, do_gelu);
    }
}

static void launch_split(const float* src, __nv_bfloat16* hi, __nv_bfloat16* lo, long n) {
    long n4 = n / 4;
    split_kernel<<<(unsigned)((n4 + 255) / 256), 256>>>(src, hi, lo, (int)n4);
}

extern "C" void kernel_launch(void* const* d_in, const int* in_sizes, int n_in,
                              void* d_out, int out_size) {
    const float* region = (const float*)d_in[0];
    const float* mask   = (const float*)d_in[1];
    const float* cls    = (const float*)d_in[2];
    const float* ln1w   = (const float*)d_in[3];
    const float* ln1b   = (const float*)d_in[4];
    const float* qkvw   = (const float*)d_in[5];
    const float* qkvb   = (const float*)d_in[6];
    const float* aow    = (const float*)d_in[7];
    const float* aob    = (const float*)d_in[8];
    const float* ln2w   = (const float*)d_in[9];
    const float* ln2b   = (const float*)d_in[10];
    const float* fw1    = (const float*)d_in[11];
    const float* fb1    = (const float*)d_in[12];
    const float* fw2    = (const float*)d_in[13];
    const float* fb2    = (const float*)d_in[14];
    const float* cw1    = (const float*)d_in[15];
    const float* cb1    = (const float*)d_in[16];
    const float* clnw   = (const float*)d_in[17];
    const float* clnb   = (const float*)d_in[18];
    const float* cw2    = (const float*)d_in[19];
    const float* cb2    = (const float*)d_in[20];
    const float* lAu    = (const float*)d_in[21];
    const float* lBu    = (const float*)d_in[22];
    const float* lAd    = (const float*)d_in[23];
    const float* lBd    = (const float*)d_in[24];
    const float* flw    = (const float*)d_in[25];
    const float* flb    = (const float*)d_in[26];
    float* out = (float*)d_out;

    cudaFuncSetAttribute((const void*)mma_gemm_v3<128, 4>,
                         cudaFuncAttributeMaxDynamicSharedMemorySize, 61440);

    // fp32 scratch addresses
    float *hs, *qkv, *res1, *bo, *h1, *aup, *G;
    cudaGetSymbolAddress((void**)&hs,   g_hs);
    cudaGetSymbolAddress((void**)&qkv,  g_qkv);
    cudaGetSymbolAddress((void**)&res1, g_res1);
    cudaGetSymbolAddress((void**)&bo,   g_bo);
    cudaGetSymbolAddress((void**)&h1,   g_h1);
    cudaGetSymbolAddress((void**)&aup,  g_aup);
    cudaGetSymbolAddress((void**)&G,    g_G);

    // plane addresses
    __nv_bfloat16 *xln_h, *xln_l, *y_h, *y_l, *ctx_h, *ctx_l, *bh_h, *bh_l, *pool_h, *pool_l;
    __nv_bfloat16 *qkvw_h, *qkvw_l, *aow_h, *aow_l, *fw1_h, *fw1_l, *fw2_h, *fw2_l;
    __nv_bfloat16 *cw1_h, *cw1_l, *lAu_h, *lAu_l, *lAd_h, *lAd_l;
    cudaGetSymbolAddress((void**)&xln_h, g_xln_h); cudaGetSymbolAddress((void**)&xln_l, g_xln_l);
    cudaGetSymbolAddress((void**)&y_h,   g_y_h);   cudaGetSymbolAddress((void**)&y_l,   g_y_l);
    cudaGetSymbolAddress((void**)&ctx_h, g_ctx_h); cudaGetSymbolAddress((void**)&ctx_l, g_ctx_l);
    cudaGetSymbolAddress((void**)&bh_h,  g_bh_h);  cudaGetSymbolAddress((void**)&bh_l,  g_bh_l);
    cudaGetSymbolAddress((void**)&pool_h, g_pool_h); cudaGetSymbolAddress((void**)&pool_l, g_pool_l);
    cudaGetSymbolAddress((void**)&qkvw_h, g_qkvw_h); cudaGetSymbolAddress((void**)&qkvw_l, g_qkvw_l);
    cudaGetSymbolAddress((void**)&aow_h, g_aow_h); cudaGetSymbolAddress((void**)&aow_l, g_aow_l);
    cudaGetSymbolAddress((void**)&fw1_h, g_fw1_h); cudaGetSymbolAddress((void**)&fw1_l, g_fw1_l);
    cudaGetSymbolAddress((void**)&fw2_h, g_fw2_h); cudaGetSymbolAddress((void**)&fw2_l, g_fw2_l);
    cudaGetSymbolAddress((void**)&cw1_h, g_cw1_h); cudaGetSymbolAddress((void**)&cw1_l, g_cw1_l);
    cudaGetSymbolAddress((void**)&lAu_h, g_lAu_h); cudaGetSymbolAddress((void**)&lAu_l, g_lAu_l);
    cudaGetSymbolAddress((void**)&lAd_h, g_lAd_h); cudaGetSymbolAddress((void**)&lAd_l, g_lAd_l);

    const int NE = MROWS * H;

    // ---- weight splits (once per launch) ----
    launch_split(qkvw, qkvw_h, qkvw_l, (long)L * 3 * H * H);
    launch_split(aow,  aow_h,  aow_l,  (long)L * H * H);
    launch_split(fw1,  fw1_h,  fw1_l,  (long)L * FF * H);
    launch_split(fw2,  fw2_h,  fw2_l,  (long)L * H * FF);
    launch_split(cw1,  cw1_h,  cw1_l,  (long)(L / 2) * D * H2 * H);
    launch_split(lAu,  lAu_h,  lAu_l,  (long)(L / 2) * E * RK * H);
    launch_split(lAd,  lAd_h,  lAd_l,  (long)(L / 2) * E * RK * FF);

    init_hs_kernel<<<(NE + 255) / 256, 256>>>(region, cls);

    for (int i = 0; i < L; i++) {
        const int j = i / 2;

        // x_ln planes = LN(hs, ln1)
        ln_planes_kernel<<<MROWS, 256>>>(hs, ln1w + (long)i * H, ln1b + (long)i * H,
                                         xln_h, xln_l, 1e-12f);

        // qkv = x_ln @ qkv_w^T + qkv_b
        launch_gemm3(xln_h, xln_l, qkvw_h + (long)i * 3 * H * H, qkvw_l + (long)i * 3 * H * H,
                     qkvb + (long)i * 3 * H, nullptr, qkv, nullptr, nullptr,
                     MROWS, 3 * H, H, 0);

        // attention -> ctx planes
        attn_kernel<<<dim3(B, NH), 256>>>();

        // res1 = ctx @ ow^T + ob + hs
        launch_gemm3(ctx_h, ctx_l, aow_h + (long)i * H * H, aow_l + (long)i * H * H,
                     aob + (long)i * H, hs, res1, nullptr, nullptr,
                     MROWS, H, H, 0);

        // y planes = LN(res1, ln2)
        ln_planes_kernel<<<MROWS, 256>>>(res1, ln2w + (long)i * H, ln2b + (long)i * H,
                                         y_h, y_l, 1e-12f);

        // bh planes = gelu(y @ w1^T + b1)
        launch_gemm3(y_h, y_l, fw1_h + (long)i * FF * H, fw1_l + (long)i * FF * H,
                     fb1 + (long)i * FF, nullptr, nullptr, bh_h, bh_l,
                     MROWS, FF, H, 1);

        if (i % 2 == 1) {
            // hs = bh @ w2^T + b2 + res1
            launch_gemm3(bh_h, bh_l, fw2_h + (long)i * H * FF, fw2_l + (long)i * H * FF,
                         fb2 + (long)i * H, res1, hs, nullptr, nullptr,
                         MROWS, H, FF, 0);
        } else {
            // base_out
            launch_gemm3(bh_h, bh_l, fw2_h + (long)i * H * FF, fw2_l + (long)i * H * FF,
                         fb2 + (long)i * H, nullptr, bo, nullptr, nullptr,
                         MROWS, H, FF, 0);

            // ---- classifier ----
            pool_kernel<<<dim3(D, B), 256>>>(mask);
            launch_gemm3(pool_h, pool_l,
                         cw1_h + (long)j * D * H2 * H, cw1_l + (long)j * D * H2 * H,
                         cb1 + (long)j * D * H2, nullptr, h1, nullptr, nullptr,
                         B, H2, H, 0, D, (long)B * H, (long)H2 * H, (long)H2, (long)B * H2);
            cls_head_kernel<<<dim3(D, B), 128>>>(clnw + (long)j * D * H2,
                                                 clnb + (long)j * D * H2,
                                                 cw2 + (long)j * D * H2,
                                                 cb2 + (long)j * D);
            w_kernel<<<(MROWS + 127) / 128, 128>>>(mask);

            // ---- LoRA (factored) ----
            launch_gemm3(y_h, y_l, lAu_h + (long)j * E * RK * H, lAu_l + (long)j * E * RK * H,
                         nullptr, nullptr, aup, nullptr, nullptr, MROWS, E * RK, H, 0);
            launch_gemm3(bh_h, bh_l, lAd_h + (long)j * E * RK * FF, lAd_l + (long)j * E * RK * FF,
                         nullptr, nullptr, G, nullptr, nullptr, MROWS, E * RK, FF, 0);
            mmat_kernel<<<E * 64, 128>>>(lAd + (long)j * E * RK * FF,
                                         lBu + (long)j * E * FF * RK);
            adn_kernel<<<(MROWS * E * RK + 255) / 256, 256>>>();
            mix_kernel<<<MROWS, 256>>>(lBd + (long)j * E * H * RK);
        }
    }

    ln_kernel<<<MROWS, 256>>>(hs, flw, flb, out, 1e-12f);
}